// round 7
// baseline (speedup 1.0000x reference)
#include <cuda_runtime.h>
#include <cuda_bf16.h>
#include <cstdint>
#include <cstddef>
#include <math.h>

// Problem constants
#define N_ROWS   384
#define BS       192
#define PD       16
#define DDIM     73728          // 32*48*48
#define INV_TEMP 10.0f
#define EPS      1e-6f

// GEMM tiling (bf16 tensor cores)
#define BM 128
#define BN 128
#define BK 64
#define STAGES 3
#define NSPLIT 48
#define KCHUNK (DDIM / NSPLIT)  // 1536
#define NIT (KCHUNK / BK)       // 24
#define NTILES 6                // upper-tri 3x3 of 128-tiles
#define SROW 72                 // padded smem row (bf16): 144B stride, 16B-aligned, conflict-free
#define STAGE_ELEMS (BM * SROW)
#define SMEM_BYTES (STAGES * 2 * STAGE_ELEMS * (int)sizeof(__nv_bfloat16))  // 108 KB

// Device scratch (no cudaMalloc allowed)
static __device__ __nv_bfloat16 g_Znh[(size_t)N_ROWS * DDIM];       // 56.6 MB bf16 Z (unnormalized)
static __device__ float g_rn[N_ROWS];
static __device__ float g_part[(size_t)NSPLIT * NTILES * BM * BN];  // split-K partials 18.9 MB
static __device__ float g_S[N_ROWS * N_ROWS];
static __device__ float g_Dsum[N_ROWS];

__inline__ __device__ float blockReduceSum(float v) {
    __shared__ float sh[33];
    int lane = threadIdx.x & 31, w = threadIdx.x >> 5;
    #pragma unroll
    for (int o = 16; o; o >>= 1) v += __shfl_down_sync(0xffffffffu, v, o);
    if (lane == 0) sh[w] = v;
    __syncthreads();
    int nw = (blockDim.x + 31) >> 5;
    v = (threadIdx.x < nw) ? sh[lane] : 0.f;
    if (w == 0) {
        #pragma unroll
        for (int o = 16; o; o >>= 1) v += __shfl_down_sync(0xffffffffu, v, o);
        if (lane == 0) sh[32] = v;
    }
    __syncthreads();
    return sh[32];
}

// Demean, round to bf16, write; norm from the ROUNDED values (consistent with GEMM).
__global__ __launch_bounds__(256) void prep_kernel(const float* __restrict__ X,
                                                   const float* __restrict__ M) {
    int row = blockIdx.x;
    int ds = (row >> 2) & 3;
    const float4* x = (const float4*)(X + (size_t)row * DDIM);
    const float4* m = (const float4*)(M + (size_t)ds * DDIM);
    uint4* z = (uint4*)(g_Znh + (size_t)row * DDIM);
    float ss = 0.f;
    for (int i = threadIdx.x; i < DDIM / 8; i += blockDim.x) {
        float4 x0 = x[2 * i], x1 = x[2 * i + 1];
        float4 m0 = m[2 * i], m1 = m[2 * i + 1];
        __nv_bfloat162 h0 = __floats2bfloat162_rn(x0.x - m0.x, x0.y - m0.y);
        __nv_bfloat162 h1 = __floats2bfloat162_rn(x0.z - m0.z, x0.w - m0.w);
        __nv_bfloat162 h2 = __floats2bfloat162_rn(x1.x - m1.x, x1.y - m1.y);
        __nv_bfloat162 h3 = __floats2bfloat162_rn(x1.z - m1.z, x1.w - m1.w);
        uint4 o;
        o.x = *(const unsigned int*)&h0; o.y = *(const unsigned int*)&h1;
        o.z = *(const unsigned int*)&h2; o.w = *(const unsigned int*)&h3;
        z[i] = o;
        float2 f0 = __bfloat1622float2(h0), f1 = __bfloat1622float2(h1);
        float2 f2 = __bfloat1622float2(h2), f3 = __bfloat1622float2(h3);
        ss += f0.x * f0.x + f0.y * f0.y + f1.x * f1.x + f1.y * f1.y
            + f2.x * f2.x + f2.y * f2.y + f3.x * f3.x + f3.y * f3.y;
    }
    float tot = blockReduceSum(ss);
    if (threadIdx.x == 0) g_rn[row] = 1.f / fmaxf(sqrtf(tot), EPS);
}

__device__ __forceinline__ void ldsm_x4(uint32_t addr, uint32_t& r0, uint32_t& r1,
                                        uint32_t& r2, uint32_t& r3) {
    asm volatile("ldmatrix.sync.aligned.m8n8.x4.shared.b16 {%0,%1,%2,%3}, [%4];"
                 : "=r"(r0), "=r"(r1), "=r"(r2), "=r"(r3) : "r"(addr));
}
__device__ __forceinline__ void mma16816(float* c, const uint32_t* a, const uint32_t* b) {
    asm volatile("mma.sync.aligned.m16n8k16.row.col.f32.bf16.bf16.f32 "
                 "{%0,%1,%2,%3}, {%4,%5,%6,%7}, {%8,%9}, {%0,%1,%2,%3};"
                 : "+f"(c[0]), "+f"(c[1]), "+f"(c[2]), "+f"(c[3])
                 : "r"(a[0]), "r"(a[1]), "r"(a[2]), "r"(a[3]), "r"(b[0]), "r"(b[1]));
}
__device__ __forceinline__ void cp16(void* smem, const void* g) {
    uint32_t s = (uint32_t)__cvta_generic_to_shared(smem);
    asm volatile("cp.async.ca.shared.global [%0], [%1], 16;" :: "r"(s), "l"(g));
}
__device__ __forceinline__ void cp_commit() {
    asm volatile("cp.async.commit_group;");
}

// Upper-tri split-K bf16 Gram GEMM, cp.async 3-stage pipeline, 2 CTAs/SM.
__global__ __launch_bounds__(256, 2) void gemm_bf16_kernel() {
    extern __shared__ __nv_bfloat16 smem[];
    __nv_bfloat16* As = smem;                            // [STAGES][BM*SROW]
    __nv_bfloat16* Bs = smem + STAGES * STAGE_ELEMS;
    static const int TI[NTILES] = {0, 0, 0, 1, 1, 2};
    static const int TJ[NTILES] = {0, 1, 2, 1, 2, 2};
    const int tp = blockIdx.x;
    const int split = blockIdx.y;
    const int bm = TI[tp] * BM, bn = TJ[tp] * BN;
    const int k0 = split * KCHUNK;
    const int tid = threadIdx.x, wid = tid >> 5, lane = tid & 31;
    const int wm = (wid >> 2) * 64, wn = (wid & 3) * 32;

    const int lrow = tid >> 3;          // 0..31 base row group
    const int lc16 = tid & 7;           // 16B chunk

    float acc[4][4][4] = {};

    auto load_stage = [&](int it, int buf) {
        const int kb = k0 + it * BK;
        __nv_bfloat16* a = As + buf * STAGE_ELEMS;
        __nv_bfloat16* b = Bs + buf * STAGE_ELEMS;
        #pragma unroll
        for (int l = 0; l < 4; l++) {
            int row = lrow + l * 32;
            cp16(a + row * SROW + lc16 * 8,
                 g_Znh + (size_t)(bm + row) * DDIM + kb + lc16 * 8);
            cp16(b + row * SROW + lc16 * 8,
                 g_Znh + (size_t)(bn + row) * DDIM + kb + lc16 * 8);
        }
        cp_commit();
    };

    #pragma unroll
    for (int s = 0; s < STAGES - 1; s++) load_stage(s, s);

    #pragma unroll 1
    for (int it = 0; it < NIT; it++) {
        const int buf = it % STAGES;
        asm volatile("cp.async.wait_group %0;" :: "n"(STAGES - 2));
        __syncthreads();
        if (it + STAGES - 1 < NIT) load_stage(it + STAGES - 1, (it + STAGES - 1) % STAGES);

        const __nv_bfloat16* a_s = As + buf * STAGE_ELEMS;
        const __nv_bfloat16* b_s = Bs + buf * STAGE_ELEMS;
        #pragma unroll
        for (int ks = 0; ks < 4; ks++) {
            uint32_t a[4][4], b[4][2];
            #pragma unroll
            for (int mi = 0; mi < 4; mi++) {
                int r = wm + mi * 16 + (lane & 15);
                int cc = ks * 16 + (lane >> 4) * 8;
                uint32_t addr = (uint32_t)__cvta_generic_to_shared(a_s + r * SROW + cc);
                ldsm_x4(addr, a[mi][0], a[mi][1], a[mi][2], a[mi][3]);
            }
            // B: one ldsm_x4 covers two adjacent n-tiles (16 rows x 16 cols)
            #pragma unroll
            for (int n2 = 0; n2 < 2; n2++) {
                int r = wn + n2 * 16 + (lane & 7) + ((lane >> 4) & 1) * 8;
                int cc = ks * 16 + ((lane >> 3) & 1) * 8;
                uint32_t addr = (uint32_t)__cvta_generic_to_shared(b_s + r * SROW + cc);
                ldsm_x4(addr, b[2 * n2][0], b[2 * n2][1], b[2 * n2 + 1][0], b[2 * n2 + 1][1]);
            }
            #pragma unroll
            for (int mi = 0; mi < 4; mi++)
                #pragma unroll
                for (int ni = 0; ni < 4; ni++)
                    mma16816(acc[mi][ni], a[mi], b[ni]);
        }
    }

    float* out = g_part + ((size_t)split * NTILES + tp) * (BM * BN);
    #pragma unroll
    for (int mi = 0; mi < 4; mi++) {
        #pragma unroll
        for (int ni = 0; ni < 4; ni++) {
            int r0 = wm + mi * 16 + (lane >> 2);
            int c0 = wn + ni * 8 + 2 * (lane & 3);
            *(float2*)&out[r0 * BN + c0]       = make_float2(acc[mi][ni][0], acc[mi][ni][1]);
            *(float2*)&out[(r0 + 8) * BN + c0] = make_float2(acc[mi][ni][2], acc[mi][ni][3]);
        }
    }
}

// One block per row a: reduce split-K partials (mirrored from upper-tri tiles),
// scale by rn[a]*rn[j], write S row, and accumulate masked exp -> Dsum[a].
__global__ __launch_bounds__(256) void reduce_dsum_kernel() {
    int a = blockIdx.x;
    int ra = a & 15;   // a % PD
    int ti = a >> 7;
    int ar = a & 127;
    float local = 0.f;
    for (int j = threadIdx.x; j < N_ROWS; j += blockDim.x) {
        int tj = j >> 7, jr = j & 127;
        int t0, t1, r, c;
        if (ti <= tj) { t0 = ti; t1 = tj; r = ar; c = jr; }
        else          { t0 = tj; t1 = ti; r = jr; c = ar; }
        int tp = (t0 == 0) ? t1 : (t0 == 1 ? 2 + t1 : 3 + t1);
        float s = 0.f;
        #pragma unroll
        for (int sp = 0; sp < NSPLIT; sp++)
            s += g_part[((size_t)sp * NTILES + tp) * (BM * BN) + r * BN + c];
        s *= g_rn[a] * g_rn[j];
        g_S[a * N_ROWS + j] = s;
        if ((j & 15) != ra) local += expf(s * INV_TEMP);
    }
    float tot = blockReduceSum(local);
    if (threadIdx.x == 0) g_Dsum[a] = tot;
}

__inline__ __device__ float pair_loss(int a, int b) {
    float num = g_S[a * N_ROWS + b] * INV_TEMP;
    float en = expf(num);
    return -(num - logf(en + g_Dsum[a])) - (num - logf(en + g_Dsum[b]));
}

__global__ __launch_bounds__(256) void loss_kernel(float* __restrict__ out) {
    int p = threadIdx.x;
    float l = 0.f;
    if (p < BS) {
        int i1 = p;
        int i2 = BS + p;
        int i3 = (p + PD) % N_ROWS;
        int i4 = (BS + p + PD) % N_ROWS;
        l = pair_loss(i1, i2) + pair_loss(i3, i4)
          + pair_loss(i1, i3) + pair_loss(i2, i4);
    }
    float tot = blockReduceSum(l);
    if (threadIdx.x == 0) out[0] = tot / 576.0f;  // N_TRANSFORMS * 3 * BS
}

extern "C" void kernel_launch(void* const* d_in, const int* in_sizes, int n_in,
                              void* d_out, int out_size) {
    const float* reg_pred = (const float*)d_in[0];
    const float* means    = (const float*)d_in[1];
    if (n_in >= 2 && in_sizes[0] < in_sizes[1]) {
        reg_pred = (const float*)d_in[1];
        means    = (const float*)d_in[0];
    }
    float* out = (float*)d_out;

    cudaFuncSetAttribute(gemm_bf16_kernel,
                         cudaFuncAttributeMaxDynamicSharedMemorySize, SMEM_BYTES);

    prep_kernel<<<N_ROWS, 256>>>(reg_pred, means);
    dim3 g(NTILES, NSPLIT);
    gemm_bf16_kernel<<<g, 256, SMEM_BYTES>>>();
    reduce_dsum_kernel<<<N_ROWS, 256>>>();
    loss_kernel<<<1, 256>>>(out);
}

// round 11
// speedup vs baseline: 1.2977x; 1.2977x over previous
#include <cuda_runtime.h>
#include <cuda_bf16.h>
#include <cstdint>
#include <cstddef>
#include <math.h>

// Problem constants
#define N_ROWS   384
#define BS       192
#define PD       16
#define DDIM     73728          // 32*48*48
#define INV_TEMP 10.0f
#define EPS      1e-6f

// Shared GEMM decomposition
#define NSPLIT 24
#define KCHUNK (DDIM / NSPLIT)  // 3072
#define NTILES 6                // upper-tri 3x3 of 128-tiles
#define BM 128
#define BN 128

// tcgen05 path config
#define TC_BK 128                           // K per stage -> 8 MMAs of K=16
#define TC_STAGES 3
#define TC_NIT (KCHUNK / TC_BK)             // 24
#define TC_TILE_BYTES (BM * TC_BK * 2)      // 32 KB
#define TC_STAGE_BYTES (2 * TC_TILE_BYTES)  // 64 KB
#define TC_SMEM (1024 + TC_STAGES * TC_STAGE_BYTES + 1024)

// mma.sync fallback config (proven R6: 99.1us)
#define MM_BK 64
#define MM_STAGES 4
#define MM_NIT (KCHUNK / MM_BK)             // 48
#define SROW 72
#define MM_STAGE_ELEMS (BM * SROW)
#define MM_SMEM (MM_STAGES * 2 * MM_STAGE_ELEMS * 2)  // 147456

#define SMEM_MAX (TC_SMEM > MM_SMEM ? TC_SMEM : MM_SMEM)

// idesc kind::f16: dtype F32, atype/btype BF16, N=128, M=128
#define MMA_IDESC ((1u << 4) | (1u << 7) | (1u << 10) | ((BN / 8) << 17) | ((BM / 16) << 24))
// SW128 K-major descriptor base: layout SW128, version 1, SBO=64, LBO=1
#define DESC_BASE ((2ull << 61) | (1ull << 46) | (64ull << 32) | (1ull << 16))
#define SW128(x) ((x) ^ (((x) >> 3) & 0x70))

// Enable tcgen05 helpers when: host pass (parse only) OR sm_103a/sm_100a device pass.
#if !defined(__CUDA_ARCH__) || defined(__CUDA_ARCH_FEAT_SM103_ALL) || defined(__CUDA_ARCH_FEAT_SM100_ALL)
#define TC_HELPERS 1
#endif
#if defined(__CUDA_ARCH__) && !defined(__CUDA_ARCH_FEAT_SM103_ALL) && !defined(__CUDA_ARCH_FEAT_SM100_ALL)
#define USE_FALLBACK_MMA 1
#endif

// Device scratch (no cudaMalloc allowed)
static __device__ __nv_bfloat16 g_Znh[(size_t)N_ROWS * DDIM];       // 56.6 MB bf16 Z (unnormalized)
static __device__ float g_rn[N_ROWS];
static __device__ float g_part[(size_t)NSPLIT * NTILES * BM * BN];  // split-K partials 9.4 MB
static __device__ float g_S[N_ROWS * N_ROWS];
static __device__ float g_Dsum[N_ROWS];

__inline__ __device__ float blockReduceSum(float v) {
    __shared__ float sh[33];
    int lane = threadIdx.x & 31, w = threadIdx.x >> 5;
    #pragma unroll
    for (int o = 16; o; o >>= 1) v += __shfl_down_sync(0xffffffffu, v, o);
    if (lane == 0) sh[w] = v;
    __syncthreads();
    int nw = (blockDim.x + 31) >> 5;
    v = (threadIdx.x < nw) ? sh[lane] : 0.f;
    if (w == 0) {
        #pragma unroll
        for (int o = 16; o; o >>= 1) v += __shfl_down_sync(0xffffffffu, v, o);
        if (lane == 0) sh[32] = v;
    }
    __syncthreads();
    return sh[32];
}

// Demean, round to bf16, write; norm from the ROUNDED values (consistent with GEMM).
__global__ __launch_bounds__(256) void prep_kernel(const float* __restrict__ X,
                                                   const float* __restrict__ M) {
    int row = blockIdx.x;
    int ds = (row >> 2) & 3;
    const float4* x = (const float4*)(X + (size_t)row * DDIM);
    const float4* m = (const float4*)(M + (size_t)ds * DDIM);
    uint4* z = (uint4*)(g_Znh + (size_t)row * DDIM);
    float ss = 0.f;
    for (int i = threadIdx.x; i < DDIM / 8; i += blockDim.x) {
        float4 x0 = x[2 * i], x1 = x[2 * i + 1];
        float4 m0 = m[2 * i], m1 = m[2 * i + 1];
        __nv_bfloat162 h0 = __floats2bfloat162_rn(x0.x - m0.x, x0.y - m0.y);
        __nv_bfloat162 h1 = __floats2bfloat162_rn(x0.z - m0.z, x0.w - m0.w);
        __nv_bfloat162 h2 = __floats2bfloat162_rn(x1.x - m1.x, x1.y - m1.y);
        __nv_bfloat162 h3 = __floats2bfloat162_rn(x1.z - m1.z, x1.w - m1.w);
        uint4 o;
        o.x = *(const unsigned int*)&h0; o.y = *(const unsigned int*)&h1;
        o.z = *(const unsigned int*)&h2; o.w = *(const unsigned int*)&h3;
        z[i] = o;
        float2 f0 = __bfloat1622float2(h0), f1 = __bfloat1622float2(h1);
        float2 f2 = __bfloat1622float2(h2), f3 = __bfloat1622float2(h3);
        ss += f0.x * f0.x + f0.y * f0.y + f1.x * f1.x + f1.y * f1.y
            + f2.x * f2.x + f2.y * f2.y + f3.x * f3.x + f3.y * f3.y;
    }
    float tot = blockReduceSum(ss);
    if (threadIdx.x == 0) g_rn[row] = 1.f / fmaxf(sqrtf(tot), EPS);
}

// ---------- common helpers ----------
__device__ __forceinline__ uint32_t smem_u32(const void* p) {
    return (uint32_t)__cvta_generic_to_shared(p);
}
__device__ __forceinline__ void cp16s(uint32_t saddr, const void* g) {
    asm volatile("cp.async.ca.shared.global [%0], [%1], 16;" :: "r"(saddr), "l"(g));
}
__device__ __forceinline__ void cp_commit() { asm volatile("cp.async.commit_group;"); }
template <int N> __device__ __forceinline__ void cp_wait() {
    asm volatile("cp.async.wait_group %0;" :: "n"(N));
}
__device__ __forceinline__ void ldsm_x4(uint32_t addr, uint32_t& r0, uint32_t& r1,
                                        uint32_t& r2, uint32_t& r3) {
    asm volatile("ldmatrix.sync.aligned.m8n8.x4.shared.b16 {%0,%1,%2,%3}, [%4];"
                 : "=r"(r0), "=r"(r1), "=r"(r2), "=r"(r3) : "r"(addr));
}
__device__ __forceinline__ void mma16816(float* c, const uint32_t* a, const uint32_t* b) {
    asm volatile("mma.sync.aligned.m16n8k16.row.col.f32.bf16.bf16.f32 "
                 "{%0,%1,%2,%3}, {%4,%5,%6,%7}, {%8,%9}, {%0,%1,%2,%3};"
                 : "+f"(c[0]), "+f"(c[1]), "+f"(c[2]), "+f"(c[3])
                 : "r"(a[0]), "r"(a[1]), "r"(a[2]), "r"(a[3]), "r"(b[0]), "r"(b[1]));
}
__device__ __forceinline__ void mbar_init(uint32_t a, uint32_t cnt) {
    asm volatile("mbarrier.init.shared.b64 [%0], %1;" :: "r"(a), "r"(cnt) : "memory");
}
__device__ __forceinline__ void mbar_wait(uint32_t a, uint32_t parity) {
    asm volatile("{\n\t.reg .pred P;\n\tLW%=:\n\t"
                 "mbarrier.try_wait.parity.shared.b64 P, [%0], %1;\n\t"
                 "@!P bra LW%=;\n\t}" :: "r"(a), "r"(parity) : "memory");
}
__device__ __forceinline__ uint32_t elect_one() {
    uint32_t pred;
    asm volatile("{\n\t.reg .pred p;\n\telect.sync _|p, 0xFFFFFFFF;\n\t"
                 "selp.b32 %0, 1, 0, p;\n\t}" : "=r"(pred));
    return pred;
}

// ---------- tcgen05 helpers (arch-specific; excluded from non-'a' device pass) ----------
#ifdef TC_HELPERS
__device__ __forceinline__ void tc_alloc(uint32_t res_addr, uint32_t ncols) {
    asm volatile("tcgen05.alloc.cta_group::1.sync.aligned.shared::cta.b32 [%0], %1;"
                 :: "r"(res_addr), "r"(ncols) : "memory");
}
__device__ __forceinline__ void tc_relinq() {
    asm volatile("tcgen05.relinquish_alloc_permit.cta_group::1.sync.aligned;");
}
__device__ __forceinline__ void tc_dealloc(uint32_t tmem, uint32_t ncols) {
    asm volatile("tcgen05.dealloc.cta_group::1.sync.aligned.b32 %0, %1;" :: "r"(tmem), "r"(ncols));
}
__device__ __forceinline__ void tc_mma_f16_ss(uint32_t d, uint64_t ad, uint64_t bd,
                                              uint32_t idesc, uint32_t en) {
    asm volatile("{\n\t.reg .pred p;\n\tsetp.ne.u32 p, %5, 0;\n\t"
                 "tcgen05.mma.cta_group::1.kind::f16 [%0], %1, %2, %3, {%4, %4, %4, %4}, p;\n\t}"
                 :: "r"(d), "l"(ad), "l"(bd), "r"(idesc), "r"(0u), "r"(en) : "memory");
}
__device__ __forceinline__ void tc_commit(uint32_t mbar) {
    asm volatile("tcgen05.commit.cta_group::1.mbarrier::arrive::one.shared::cluster.b64 [%0];"
                 :: "r"(mbar) : "memory");
}
__device__ __forceinline__ void fence_async_shared() {
    asm volatile("fence.proxy.async.shared::cta;" ::: "memory");
}
__device__ __forceinline__ void tc_fence_after() {
    asm volatile("tcgen05.fence::after_thread_sync;" ::: "memory");
}
__device__ __forceinline__ void tc_ld_x32(uint32_t* r, uint32_t tmem) {
    asm volatile("tcgen05.ld.sync.aligned.32x32b.x32.b32 "
                 "{%0,%1,%2,%3,%4,%5,%6,%7,%8,%9,%10,%11,%12,%13,%14,%15,"
                 "%16,%17,%18,%19,%20,%21,%22,%23,%24,%25,%26,%27,%28,%29,%30,%31}, [%32];"
                 : "=r"(r[0]), "=r"(r[1]), "=r"(r[2]), "=r"(r[3]), "=r"(r[4]), "=r"(r[5]),
                   "=r"(r[6]), "=r"(r[7]), "=r"(r[8]), "=r"(r[9]), "=r"(r[10]), "=r"(r[11]),
                   "=r"(r[12]), "=r"(r[13]), "=r"(r[14]), "=r"(r[15]), "=r"(r[16]), "=r"(r[17]),
                   "=r"(r[18]), "=r"(r[19]), "=r"(r[20]), "=r"(r[21]), "=r"(r[22]), "=r"(r[23]),
                   "=r"(r[24]), "=r"(r[25]), "=r"(r[26]), "=r"(r[27]), "=r"(r[28]), "=r"(r[29]),
                   "=r"(r[30]), "=r"(r[31])
                 : "r"(tmem));
}
__device__ __forceinline__ void tc_wait_ld() {
    asm volatile("tcgen05.wait::ld.sync.aligned;" ::: "memory");
}
#endif  // TC_HELPERS

// Upper-tri split-K bf16 Gram GEMM. tcgen05 on sm_103a; mma.sync fallback otherwise.
__global__ __launch_bounds__(256, 1) __cluster_dims__(1, 1, 1)
void gemm_kernel() {
    extern __shared__ char smem[];
    static const int TI[NTILES] = {0, 0, 0, 1, 1, 2};
    static const int TJ[NTILES] = {0, 1, 2, 1, 2, 2};
    const int tp = blockIdx.x;
    const int split = blockIdx.y;
    const int bm = TI[tp] * BM, bn = TJ[tp] * BN;
    const int k0 = split * KCHUNK;
    const int tid = threadIdx.x, wid = tid >> 5, lane = tid & 31;

#ifdef USE_FALLBACK_MMA
    // ================= mma.sync fallback (R6, proven) =================
    __nv_bfloat16* As = (__nv_bfloat16*)smem;
    __nv_bfloat16* Bs = (__nv_bfloat16*)smem + MM_STAGES * MM_STAGE_ELEMS;
    const int wm = (wid >> 2) * 64, wn = (wid & 3) * 32;
    const int lrow = tid >> 3, lc16 = tid & 7;
    float acc[4][4][4] = {};

    auto load_stage = [&](int it, int buf) {
        const int kb = k0 + it * MM_BK;
        __nv_bfloat16* a = As + buf * MM_STAGE_ELEMS;
        __nv_bfloat16* b = Bs + buf * MM_STAGE_ELEMS;
        #pragma unroll
        for (int l = 0; l < 4; l++) {
            int row = lrow + l * 32;
            cp16s(smem_u32(a + row * SROW + lc16 * 8),
                  g_Znh + (size_t)(bm + row) * DDIM + kb + lc16 * 8);
            cp16s(smem_u32(b + row * SROW + lc16 * 8),
                  g_Znh + (size_t)(bn + row) * DDIM + kb + lc16 * 8);
        }
        cp_commit();
    };

    #pragma unroll
    for (int s = 0; s < MM_STAGES - 1; s++) load_stage(s, s);

    #pragma unroll 1
    for (int it = 0; it < MM_NIT; it++) {
        const int buf = it % MM_STAGES;
        cp_wait<MM_STAGES - 2>();
        __syncthreads();
        if (it + MM_STAGES - 1 < MM_NIT)
            load_stage(it + MM_STAGES - 1, (it + MM_STAGES - 1) % MM_STAGES);

        const __nv_bfloat16* a_s = As + buf * MM_STAGE_ELEMS;
        const __nv_bfloat16* b_s = Bs + buf * MM_STAGE_ELEMS;
        #pragma unroll
        for (int ks = 0; ks < 4; ks++) {
            uint32_t a[4][4], b[4][2];
            #pragma unroll
            for (int mi = 0; mi < 4; mi++) {
                int r = wm + mi * 16 + (lane & 15);
                int cc = ks * 16 + (lane >> 4) * 8;
                ldsm_x4(smem_u32(a_s + r * SROW + cc), a[mi][0], a[mi][1], a[mi][2], a[mi][3]);
            }
            #pragma unroll
            for (int n2 = 0; n2 < 2; n2++) {
                int r = wn + n2 * 16 + (lane & 7) + ((lane >> 4) & 1) * 8;
                int cc = ks * 16 + ((lane >> 3) & 1) * 8;
                ldsm_x4(smem_u32(b_s + r * SROW + cc),
                        b[2 * n2][0], b[2 * n2][1], b[2 * n2 + 1][0], b[2 * n2 + 1][1]);
            }
            #pragma unroll
            for (int mi = 0; mi < 4; mi++)
                #pragma unroll
                for (int ni = 0; ni < 4; ni++)
                    mma16816(acc[mi][ni], a[mi], b[ni]);
        }
    }

    float* out = g_part + ((size_t)split * NTILES + tp) * (BM * BN);
    #pragma unroll
    for (int mi = 0; mi < 4; mi++)
        #pragma unroll
        for (int ni = 0; ni < 4; ni++) {
            int r0 = wm + mi * 16 + (lane >> 2);
            int c0 = wn + ni * 8 + 2 * (lane & 3);
            *(float2*)&out[r0 * BN + c0]       = make_float2(acc[mi][ni][0], acc[mi][ni][1]);
            *(float2*)&out[(r0 + 8) * BN + c0] = make_float2(acc[mi][ni][2], acc[mi][ni][3]);
        }
#else
    // ================= tcgen05 path (sm_103a) =================
    const uint32_t sbase = smem_u32(smem);
    const uint32_t tiles = (sbase + 1023u) & ~1023u;
    const uint32_t ctrl  = tiles + TC_STAGES * TC_STAGE_BYTES;   // tmem ptr slot
    const uint32_t mbar0 = ctrl + 16;                            // TC_STAGES stage mbars + 1 final

    if (wid == 0) { tc_alloc(ctrl, 128); tc_relinq(); }
    if (tid == 0) {
        #pragma unroll
        for (int s = 0; s <= TC_STAGES; s++) mbar_init(mbar0 + 8 * s, 1);
    }
    __syncthreads();
    uint32_t tmem;
    asm volatile("ld.shared.b32 %0, [%1];" : "=r"(tmem) : "r"(ctrl));

    // SW128 blocked-atom layout: atom = 8 rows x 128B; 16 atom-rows, 2 atom-cols.
    auto load_stage = [&](int s) {
        const int kb = k0 + s * TC_BK;
        const uint32_t buf = tiles + (s % TC_STAGES) * TC_STAGE_BYTES;
        #pragma unroll
        for (int l = 0; l < 16; l++) {
            int idx = tid + l * 256;            // 0..4095
            int isB = idx >> 11;                // 0:A 1:B
            int rr  = (idx >> 4) & 127;
            int c16 = idx & 15;
            uint32_t byte_off = (uint32_t)(((rr >> 3) + (c16 >> 3) * 16) * 1024
                                           + (rr & 7) * 128 + (c16 & 7) * 16);
            uint32_t dst = buf + isB * TC_TILE_BYTES + SW128(byte_off);
            cp16s(dst, g_Znh + (size_t)((isB ? bn : bm) + rr) * DDIM + kb + c16 * 8);
        }
        cp_commit();
    };

    #pragma unroll
    for (int s = 0; s < TC_STAGES - 1; s++) load_stage(s);

    #pragma unroll 1
    for (int it = 0; it < TC_NIT; it++) {
        const int buf = it % TC_STAGES;
        cp_wait<TC_STAGES - 2>();
        __syncthreads();
        if (wid == 0) {
            fence_async_shared();
            if (elect_one()) {
                uint64_t ad = DESC_BASE | (((uint64_t)((tiles + buf * TC_STAGE_BYTES) >> 4)) & 0x3FFF);
                uint64_t bd = DESC_BASE |
                    (((uint64_t)((tiles + buf * TC_STAGE_BYTES + TC_TILE_BYTES) >> 4)) & 0x3FFF);
                #pragma unroll
                for (int k = 0; k < 8; k++) {
                    uint64_t off = (uint64_t)((k & 3) * 2 + (k >> 2) * 1024);
                    tc_mma_f16_ss(tmem, ad + off, bd + off, MMA_IDESC, (it > 0 || k > 0) ? 1u : 0u);
                }
                tc_commit(mbar0 + 8 * buf);
            }
        }
        int nl = it + TC_STAGES - 1;
        if (nl < TC_NIT) {
            if (nl >= TC_STAGES) mbar_wait(mbar0 + 8 * (nl % TC_STAGES), ((nl / TC_STAGES) - 1) & 1);
            load_stage(nl);
        }
    }

    if (wid == 0 && elect_one()) tc_commit(mbar0 + 8 * TC_STAGES);
    __syncthreads();
    mbar_wait(mbar0 + 8 * TC_STAGES, 0);
    tc_fence_after();

    if (wid < 4) {
        float* out = g_part + ((size_t)split * NTILES + tp) * (BM * BN);
        int row = wid * 32 + lane;
        #pragma unroll
        for (int ch = 0; ch < 4; ch++) {
            uint32_t r[32];
            tc_ld_x32(r, tmem + ch * 32);
            tc_wait_ld();
            #pragma unroll
            for (int c = 0; c < 32; c++)
                out[(size_t)row * BN + ch * 32 + c] = __uint_as_float(r[c]);
        }
    }
    __syncthreads();
    if (wid == 0) tc_dealloc(tmem, 128);
#endif
}

// One block per row a: reduce split-K partials (mirrored from upper-tri tiles),
// scale by rn[a]*rn[j], write S row, and accumulate masked exp -> Dsum[a].
__global__ __launch_bounds__(256) void reduce_dsum_kernel() {
    int a = blockIdx.x;
    int ra = a & 15;   // a % PD
    int ti = a >> 7;
    int ar = a & 127;
    float local = 0.f;
    for (int j = threadIdx.x; j < N_ROWS; j += blockDim.x) {
        int tj = j >> 7, jr = j & 127;
        int t0, t1, r, c;
        if (ti <= tj) { t0 = ti; t1 = tj; r = ar; c = jr; }
        else          { t0 = tj; t1 = ti; r = jr; c = ar; }
        int tp = (t0 == 0) ? t1 : (t0 == 1 ? 2 + t1 : 3 + t1);
        float s = 0.f;
        #pragma unroll
        for (int sp = 0; sp < NSPLIT; sp++)
            s += g_part[((size_t)sp * NTILES + tp) * (BM * BN) + r * BN + c];
        s *= g_rn[a] * g_rn[j];
        g_S[a * N_ROWS + j] = s;
        if ((j & 15) != ra) local += expf(s * INV_TEMP);
    }
    float tot = blockReduceSum(local);
    if (threadIdx.x == 0) g_Dsum[a] = tot;
}

__inline__ __device__ float pair_loss(int a, int b) {
    float num = g_S[a * N_ROWS + b] * INV_TEMP;
    float en = expf(num);
    return -(num - logf(en + g_Dsum[a])) - (num - logf(en + g_Dsum[b]));
}

__global__ __launch_bounds__(256) void loss_kernel(float* __restrict__ out) {
    int p = threadIdx.x;
    float l = 0.f;
    if (p < BS) {
        int i1 = p;
        int i2 = BS + p;
        int i3 = (p + PD) % N_ROWS;
        int i4 = (BS + p + PD) % N_ROWS;
        l = pair_loss(i1, i2) + pair_loss(i3, i4)
          + pair_loss(i1, i3) + pair_loss(i2, i4);
    }
    float tot = blockReduceSum(l);
    if (threadIdx.x == 0) out[0] = tot / 576.0f;  // N_TRANSFORMS * 3 * BS
}

extern "C" void kernel_launch(void* const* d_in, const int* in_sizes, int n_in,
                              void* d_out, int out_size) {
    const float* reg_pred = (const float*)d_in[0];
    const float* means    = (const float*)d_in[1];
    if (n_in >= 2 && in_sizes[0] < in_sizes[1]) {
        reg_pred = (const float*)d_in[1];
        means    = (const float*)d_in[0];
    }
    float* out = (float*)d_out;

    cudaFuncSetAttribute(gemm_kernel,
                         cudaFuncAttributeMaxDynamicSharedMemorySize, SMEM_MAX);

    prep_kernel<<<N_ROWS, 256>>>(reg_pred, means);
    dim3 g(NTILES, NSPLIT);
    gemm_kernel<<<g, 256, SMEM_MAX>>>();
    reduce_dsum_kernel<<<N_ROWS, 256>>>();
    loss_kernel<<<1, 256>>>(out);
}